// round 3
// baseline (speedup 1.0000x reference)
#include <cuda_runtime.h>
#include <cstdint>
#include <cstddef>

// Problem constants
#define S_DIM 128
#define N_DIM 256
#define C_DIM 256
#define H_DIM 8
#define DH_DIM 32
#define PD_DIM 128
#define ROWS (S_DIM * N_DIM)          // 32768 token rows
#define QKV_N 768                      // 3*C
#define ATT_SCALE 0.17677669529663687f // 32^-0.5
#define NEGV (-1000000000.0f)
#define LN_EPS 1e-5f

// ---------------------------------------------------------------------------
// Scratch (static device allocations — no runtime malloc allowed).
// g_qkv is dead after the attention kernel; the out-projection reuses its
// first ROWS*C_DIM floats as its destination (disjoint lifetimes).
// ---------------------------------------------------------------------------
__device__ float g_qkv[(size_t)ROWS * QKV_N];              // 100.7 MB
__device__ float g_biasT[(size_t)H_DIM * N_DIM * N_DIM];   // 2 MB, layout [h][m][n]
__device__ float g_att[(size_t)ROWS * C_DIM];              // 33.6 MB
__device__ int   g_mask[ROWS];
__device__ int   g_mask_mode;

// ---------------------------------------------------------------------------
// Mask dtype detection: reference mask is jax bool; on-wire it may arrive as
// int32, uint8/bool, or float32. Detect from the first 1024 bytes (always
// in-bounds for every candidate dtype: bool size = 32768 bytes).
// ---------------------------------------------------------------------------
__global__ void detect_mask_kernel(const unsigned char* __restrict__ p) {
    if (threadIdx.x == 0) {
        const unsigned int* w = (const unsigned int*)p;
        bool is_i32 = true, is_f32 = true;
        for (int i = 0; i < 256; i++) {
            unsigned int v = w[i];
            if (v > 1u) is_i32 = false;
            if (v != 0u && v != 0x3f800000u) is_f32 = false;
        }
        g_mask_mode = is_i32 ? 0 : (is_f32 ? 2 : 1);
    }
}

__global__ void norm_mask_kernel(const void* __restrict__ p) {
    int i = blockIdx.x * blockDim.x + threadIdx.x;
    if (i >= ROWS) return;
    int mode = g_mask_mode;
    int v;
    if (mode == 0)      v = (((const int*)p)[i] != 0);
    else if (mode == 1) v = (((const unsigned char*)p)[i] != 0);
    else                v = (((const float*)p)[i] != 0.0f);
    g_mask[i] = v;
}

// ---------------------------------------------------------------------------
// Pair bias: biasT[h][m][n] = dot(pair[n][m][:], pb_w[h][:]) + pb_b[h]
// Stored transposed so the attention inner loop (fixed m, n = thread) reads
// it coalesced. Grid: one block per m, 256 threads = n.
// ---------------------------------------------------------------------------
__global__ void pair_bias_kernel(const float* __restrict__ pair,
                                 const float* __restrict__ pb_w,
                                 const float* __restrict__ pb_b) {
    __shared__ float w[H_DIM][PD_DIM];
    __shared__ float bb[H_DIM];
    int tid = threadIdx.x;
    for (int i = tid; i < H_DIM * PD_DIM; i += 256) w[i >> 7][i & 127] = pb_w[i];
    if (tid < H_DIM) bb[tid] = pb_b[tid];
    __syncthreads();

    int m = blockIdx.x;
    int n = tid;
    const float4* pr = (const float4*)(pair + ((size_t)n * N_DIM + m) * PD_DIM);
    float acc[H_DIM];
#pragma unroll
    for (int h = 0; h < H_DIM; h++) acc[h] = bb[h];
#pragma unroll 4
    for (int dv = 0; dv < PD_DIM / 4; dv++) {
        float4 pv = pr[dv];
#pragma unroll
        for (int h = 0; h < H_DIM; h++) {
            float4 wv = *(const float4*)&w[h][dv * 4];
            acc[h] += pv.x * wv.x + pv.y * wv.y + pv.z * wv.z + pv.w * wv.w;
        }
    }
#pragma unroll
    for (int h = 0; h < H_DIM; h++)
        g_biasT[((size_t)h * N_DIM + m) * N_DIM + n] = acc[h];
}

// ---------------------------------------------------------------------------
// Tiled fp32 GEMM (NT): C[M,N] = A[M,K] @ W[N,K]^T + bias[N]
// BM=BN=128, BK=16, 256 threads, 8x8 microtile per thread.
// Smem tiles padded (+4) to avoid 4-way bank conflicts on microtile reads.
// M % 128 == 0, N % 128 == 0, K % 16 == 0 (holds for all call sites).
// ---------------------------------------------------------------------------
template <int BM, int BN, int BK>
__global__ void gemm_nt_kernel(const float* __restrict__ A,
                               const float* __restrict__ W,
                               const float* __restrict__ bvec,
                               float* __restrict__ C,
                               int M, int N, int K) {
    __shared__ float As[BK][BM + 4];
    __shared__ float Bs[BK][BN + 4];
    const int tid  = threadIdx.x;
    const int row0 = blockIdx.y * BM;
    const int col0 = blockIdx.x * BN;
    const int ty = tid >> 4;   // 0..15
    const int tx = tid & 15;   // 0..15

    float acc[8][8];
#pragma unroll
    for (int i = 0; i < 8; i++)
#pragma unroll
        for (int j = 0; j < 8; j++) acc[i][j] = 0.0f;

    for (int kt = 0; kt < K; kt += BK) {
#pragma unroll
        for (int r = 0; r < (BM * BK) / (256 * 4); r++) {
            int idx  = tid + r * 256;
            int arow = idx >> 2;          // 0..127
            int akq  = (idx & 3) << 2;    // {0,4,8,12}
            float4 av = *(const float4*)(A + (size_t)(row0 + arow) * K + kt + akq);
            As[akq + 0][arow] = av.x; As[akq + 1][arow] = av.y;
            As[akq + 2][arow] = av.z; As[akq + 3][arow] = av.w;
            float4 bv = *(const float4*)(W + (size_t)(col0 + arow) * K + kt + akq);
            Bs[akq + 0][arow] = bv.x; Bs[akq + 1][arow] = bv.y;
            Bs[akq + 2][arow] = bv.z; Bs[akq + 3][arow] = bv.w;
        }
        __syncthreads();
#pragma unroll
        for (int kk = 0; kk < BK; kk++) {
            float4 a0 = *(const float4*)&As[kk][ty * 8];
            float4 a1 = *(const float4*)&As[kk][ty * 8 + 4];
            float4 b0 = *(const float4*)&Bs[kk][tx * 8];
            float4 b1 = *(const float4*)&Bs[kk][tx * 8 + 4];
            float a[8] = {a0.x, a0.y, a0.z, a0.w, a1.x, a1.y, a1.z, a1.w};
            float b[8] = {b0.x, b0.y, b0.z, b0.w, b1.x, b1.y, b1.z, b1.w};
#pragma unroll
            for (int i = 0; i < 8; i++)
#pragma unroll
                for (int j = 0; j < 8; j++) acc[i][j] += a[i] * b[j];
        }
        __syncthreads();
    }

    float bj[8];
#pragma unroll
    for (int j = 0; j < 8; j++) bj[j] = bvec[col0 + tx * 8 + j];
#pragma unroll
    for (int i = 0; i < 8; i++) {
        float* cp = C + (size_t)(row0 + ty * 8 + i) * N + col0 + tx * 8;
        float4 v0 = make_float4(acc[i][0] + bj[0], acc[i][1] + bj[1],
                                acc[i][2] + bj[2], acc[i][3] + bj[3]);
        float4 v1 = make_float4(acc[i][4] + bj[4], acc[i][5] + bj[5],
                                acc[i][6] + bj[6], acc[i][7] + bj[7]);
        *(float4*)cp       = v0;
        *(float4*)(cp + 4) = v1;
    }
}

// ---------------------------------------------------------------------------
// Fused attention. Grid: (h, s). 256 threads; thread n owns output row n.
// K,V tiles in dynamic smem (broadcast reads), Q + accumulator in registers.
// Chunked online softmax (chunk of 8 m) amortizes the rescale.
// logits = (mask_n && mask_m ? qk*SCALE : NEG) + biasT[h][m][n]  (exact ref order)
// ---------------------------------------------------------------------------
__global__ void attn_fused_kernel() {
    extern __shared__ float sm[];
    float* ks = sm;                         // [256][32]
    float* vs = sm + N_DIM * DH_DIM;        // [256][32]
    int*   mk = (int*)(sm + 2 * N_DIM * DH_DIM);  // [256]

    const int h = blockIdx.x;
    const int s = blockIdx.y;
    const int n = threadIdx.x;

    const size_t base = ((size_t)(s * N_DIM + n)) * QKV_N + h * DH_DIM;
    float q[DH_DIM];
    {
        const float4* gq = (const float4*)(g_qkv + base);
        float4* qr = (float4*)q;
#pragma unroll
        for (int i = 0; i < 8; i++) qr[i] = gq[i];
        const float4* gk = (const float4*)(g_qkv + base + C_DIM);
        float4* kr = (float4*)(ks + n * DH_DIM);
#pragma unroll
        for (int i = 0; i < 8; i++) kr[i] = gk[i];
        const float4* gv = (const float4*)(g_qkv + base + 2 * C_DIM);
        float4* vr = (float4*)(vs + n * DH_DIM);
#pragma unroll
        for (int i = 0; i < 8; i++) vr[i] = gv[i];
        mk[n] = g_mask[s * N_DIM + n];
    }
    __syncthreads();

    const int mybit = mk[n];
    const float* biasT = g_biasT + (size_t)h * N_DIM * N_DIM;  // [m][n]

    float o[DH_DIM];
#pragma unroll
    for (int d = 0; d < DH_DIM; d++) o[d] = 0.0f;
    float mx = -3.0e38f;
    float l  = 0.0f;

    for (int m0 = 0; m0 < N_DIM; m0 += 8) {
        float sv[8];
#pragma unroll
        for (int j = 0; j < 8; j++) {
            const int m = m0 + j;
            const float4* kr = (const float4*)(ks + m * DH_DIM);
            float acc = 0.0f;
#pragma unroll
            for (int dv = 0; dv < 8; dv++) {
                float4 kv = kr[dv];
                acc += q[dv * 4 + 0] * kv.x + q[dv * 4 + 1] * kv.y +
                       q[dv * 4 + 2] * kv.z + q[dv * 4 + 3] * kv.w;
            }
            acc *= ATT_SCALE;
            if (!(mybit && mk[m])) acc = NEGV;
            sv[j] = acc + biasT[m * N_DIM + n];
        }
        float cm = mx;
#pragma unroll
        for (int j = 0; j < 8; j++) cm = fmaxf(cm, sv[j]);
        float sc = __expf(mx - cm);
        l *= sc;
#pragma unroll
        for (int d = 0; d < DH_DIM; d++) o[d] *= sc;
#pragma unroll
        for (int j = 0; j < 8; j++) {
            float p = __expf(sv[j] - cm);
            l += p;
            const float4* vr = (const float4*)(vs + (m0 + j) * DH_DIM);
#pragma unroll
            for (int dv = 0; dv < 8; dv++) {
                float4 vv = vr[dv];
                o[dv * 4 + 0] += p * vv.x; o[dv * 4 + 1] += p * vv.y;
                o[dv * 4 + 2] += p * vv.z; o[dv * 4 + 3] += p * vv.w;
            }
        }
        mx = cm;
    }

    const float inv = 1.0f / l;
    float4* op = (float4*)(g_att + ((size_t)(s * N_DIM + n)) * C_DIM + h * DH_DIM);
#pragma unroll
    for (int dv = 0; dv < 8; dv++) {
        op[dv] = make_float4(o[dv * 4 + 0] * inv, o[dv * 4 + 1] * inv,
                             o[dv * 4 + 2] * inv, o[dv * 4 + 3] * inv);
    }
}

// ---------------------------------------------------------------------------
// Residual + LayerNorm. One block (256 threads) per row.
// Reads projected output from the reused g_qkv scratch.
// ---------------------------------------------------------------------------
__global__ void ln_kernel(const float* __restrict__ msa,
                          const float* __restrict__ gamma,
                          const float* __restrict__ beta,
                          float* __restrict__ out) {
    __shared__ float red[8];
    const int row = blockIdx.x;
    const int j = threadIdx.x;
    const size_t idx = (size_t)row * C_DIM + j;

    float x = msa[idx] + g_qkv[idx];

    float s = x;
#pragma unroll
    for (int o = 16; o > 0; o >>= 1) s += __shfl_xor_sync(0xffffffffu, s, o);
    if ((j & 31) == 0) red[j >> 5] = s;
    __syncthreads();
    float tot = 0.0f;
#pragma unroll
    for (int w = 0; w < 8; w++) tot += red[w];
    const float mu = tot * (1.0f / C_DIM);
    const float d  = x - mu;

    __syncthreads();
    float v = d * d;
#pragma unroll
    for (int o = 16; o > 0; o >>= 1) v += __shfl_xor_sync(0xffffffffu, v, o);
    if ((j & 31) == 0) red[j >> 5] = v;
    __syncthreads();
    float vt = 0.0f;
#pragma unroll
    for (int w = 0; w < 8; w++) vt += red[w];
    const float var = vt * (1.0f / C_DIM);

    out[idx] = d * rsqrtf(var + LN_EPS) * gamma[j] + beta[j];
}

// ---------------------------------------------------------------------------
// Launch
// ---------------------------------------------------------------------------
#define ATTN_SMEM ((2 * N_DIM * DH_DIM) * 4 + N_DIM * 4)  // 66560 bytes

extern "C" void kernel_launch(void* const* d_in, const int* in_sizes, int n_in,
                              void* d_out, int out_size) {
    const float* msa   = (const float*)d_in[0];
    const float* pair  = (const float*)d_in[1];
    const void*  maskp = d_in[2];
    const float* qkv_w = (const float*)d_in[3];
    const float* qkv_b = (const float*)d_in[4];
    const float* out_w = (const float*)d_in[5];
    const float* out_b = (const float*)d_in[6];
    const float* pb_w  = (const float*)d_in[7];
    const float* pb_b  = (const float*)d_in[8];
    const float* gamma = (const float*)d_in[9];
    const float* beta  = (const float*)d_in[10];
    float* out = (float*)d_out;

    (void)in_sizes; (void)n_in; (void)out_size;

    cudaFuncSetAttribute(attn_fused_kernel,
                         cudaFuncAttributeMaxDynamicSharedMemorySize, ATTN_SMEM);

    void *p_qkv = nullptr, *p_att = nullptr;
    cudaGetSymbolAddress(&p_qkv, g_qkv);
    cudaGetSymbolAddress(&p_att, g_att);

    detect_mask_kernel<<<1, 32>>>((const unsigned char*)maskp);
    norm_mask_kernel<<<ROWS / 256, 256>>>(maskp);
    pair_bias_kernel<<<N_DIM, 256>>>(pair, pb_w, pb_b);

    // QKV projection: [32768,256] x [768,256]^T -> [32768,768]
    gemm_nt_kernel<128, 128, 16><<<dim3(QKV_N / 128, ROWS / 128), 256>>>(
        msa, qkv_w, qkv_b, (float*)p_qkv, ROWS, QKV_N, C_DIM);

    // Fused attention per (h, s)
    attn_fused_kernel<<<dim3(H_DIM, S_DIM), 256, ATTN_SMEM>>>();

    // Output projection: [32768,256] x [256,256]^T -> [32768,256]
    // Destination reuses g_qkv scratch (qkv values are dead after attention).
    gemm_nt_kernel<128, 128, 16><<<dim3(C_DIM / 128, ROWS / 128), 256>>>(
        (const float*)p_att, out_w, out_b, (float*)p_qkv, ROWS, C_DIM, C_DIM);

    // Residual + LayerNorm -> d_out
    ln_kernel<<<ROWS, 256>>>(msa, gamma, beta, out);
}

// round 6
// speedup vs baseline: 1.3507x; 1.3507x over previous
#include <cuda_runtime.h>
#include <cuda_bf16.h>
#include <cstdint>
#include <cstddef>

// Problem constants
#define S_DIM 128
#define N_DIM 256
#define C_DIM 256
#define H_DIM 8
#define DH_DIM 32
#define PD_DIM 128
#define ROWS (S_DIM * N_DIM)          // 32768 token rows
#define QKV_N 768                      // 3*C
#define ATT_SCALE 0.17677669529663687f // 32^-0.5
#define NEGV (-1000000000.0f)
#define LN_EPS 1e-5f

// ---------------------------------------------------------------------------
// Scratch (static device allocations — no runtime malloc allowed).
// g_qkv is dead after the attention kernel; the out-projection reuses its
// first ROWS*C_DIM floats as its destination (disjoint lifetimes).
// ---------------------------------------------------------------------------
__device__ float g_qkv[(size_t)ROWS * QKV_N];              // 100.7 MB
__device__ float g_biasT[(size_t)H_DIM * N_DIM * N_DIM];   // 2 MB, layout [h][m][n]
__device__ float g_att[(size_t)ROWS * C_DIM];              // 33.6 MB
__device__ int   g_mask[ROWS];
__device__ int   g_mask_mode;

// ---------------------------------------------------------------------------
// Mask dtype detection (jax bool on-wire may be int32 / byte / float32).
// ---------------------------------------------------------------------------
__global__ void detect_mask_kernel(const unsigned char* __restrict__ p) {
    if (threadIdx.x == 0) {
        const unsigned int* w = (const unsigned int*)p;
        bool is_i32 = true, is_f32 = true;
        for (int i = 0; i < 256; i++) {
            unsigned int v = w[i];
            if (v > 1u) is_i32 = false;
            if (v != 0u && v != 0x3f800000u) is_f32 = false;
        }
        g_mask_mode = is_i32 ? 0 : (is_f32 ? 2 : 1);
    }
}

__global__ void norm_mask_kernel(const void* __restrict__ p) {
    int i = blockIdx.x * blockDim.x + threadIdx.x;
    if (i >= ROWS) return;
    int mode = g_mask_mode;
    int v;
    if (mode == 0)      v = (((const int*)p)[i] != 0);
    else if (mode == 1) v = (((const unsigned char*)p)[i] != 0);
    else                v = (((const float*)p)[i] != 0.0f);
    g_mask[i] = v;
}

// ---------------------------------------------------------------------------
// Pair bias: biasT[h][m][n] = dot(pair[n][m][:], pb_w[h][:]) + pb_b[h]
// ---------------------------------------------------------------------------
__global__ void pair_bias_kernel(const float* __restrict__ pair,
                                 const float* __restrict__ pb_w,
                                 const float* __restrict__ pb_b) {
    __shared__ float w[H_DIM][PD_DIM];
    __shared__ float bb[H_DIM];
    int tid = threadIdx.x;
    for (int i = tid; i < H_DIM * PD_DIM; i += 256) w[i >> 7][i & 127] = pb_w[i];
    if (tid < H_DIM) bb[tid] = pb_b[tid];
    __syncthreads();

    int m = blockIdx.x;
    int n = tid;
    const float4* pr = (const float4*)(pair + ((size_t)n * N_DIM + m) * PD_DIM);
    float acc[H_DIM];
#pragma unroll
    for (int h = 0; h < H_DIM; h++) acc[h] = bb[h];
#pragma unroll 4
    for (int dv = 0; dv < PD_DIM / 4; dv++) {
        float4 pv = pr[dv];
#pragma unroll
        for (int h = 0; h < H_DIM; h++) {
            float4 wv = *(const float4*)&w[h][dv * 4];
            acc[h] += pv.x * wv.x + pv.y * wv.y + pv.z * wv.z + pv.w * wv.w;
        }
    }
#pragma unroll
    for (int h = 0; h < H_DIM; h++)
        g_biasT[((size_t)h * N_DIM + m) * N_DIM + n] = acc[h];
}

// ---------------------------------------------------------------------------
// Tensor-core GEMM (NT): C[M,N] = A[M,K] @ W[N,K]^T + bias[N]
// bf16 hi/lo split (3 mma passes) for near-fp32 accuracy on tensor cores.
// CTA tile 128x128x32, 8 warps (2x4), warp tile 64x32, mma.m16n8k16.
// Smem stride 40 halves => conflict-free ldmatrix (all 32 banks distinct).
// Requires: M%128==0, N%128==0, K%32==0.
// ---------------------------------------------------------------------------
#define LDT 40  // padded smem row stride in bf16 elements (32 data + 8 pad)

__device__ __forceinline__ void mma_bf16(float* c, const uint32_t* a, const uint32_t* b) {
    asm volatile(
        "mma.sync.aligned.m16n8k16.row.col.f32.bf16.bf16.f32 "
        "{%0,%1,%2,%3}, {%4,%5,%6,%7}, {%8,%9}, {%0,%1,%2,%3};"
        : "+f"(c[0]), "+f"(c[1]), "+f"(c[2]), "+f"(c[3])
        : "r"(a[0]), "r"(a[1]), "r"(a[2]), "r"(a[3]), "r"(b[0]), "r"(b[1]));
}

__device__ __forceinline__ void ldsm_x4(uint32_t* r, uint32_t addr) {
    asm volatile("ldmatrix.sync.aligned.m8n8.x4.shared.b16 {%0,%1,%2,%3}, [%4];"
                 : "=r"(r[0]), "=r"(r[1]), "=r"(r[2]), "=r"(r[3]) : "r"(addr));
}

__device__ __forceinline__ void ldsm_x2(uint32_t* r, uint32_t addr) {
    asm volatile("ldmatrix.sync.aligned.m8n8.x2.shared.b16 {%0,%1}, [%2];"
                 : "=r"(r[0]), "=r"(r[1]) : "r"(addr));
}

__device__ __forceinline__ uint32_t pack_bf16(__nv_bfloat16 a, __nv_bfloat16 b) {
    __nv_bfloat162 t = __halves2bfloat162(a, b);
    return *(uint32_t*)&t;
}

__global__ __launch_bounds__(256)
void gemm_bf16x3_nt(const float* __restrict__ A,
                    const float* __restrict__ W,
                    const float* __restrict__ bvec,
                    float* __restrict__ C,
                    int M, int N, int K) {
    __shared__ __align__(16) uint16_t As_hi[128 * LDT];
    __shared__ __align__(16) uint16_t As_lo[128 * LDT];
    __shared__ __align__(16) uint16_t Bs_hi[128 * LDT];
    __shared__ __align__(16) uint16_t Bs_lo[128 * LDT];

    const int tid  = threadIdx.x;
    const int lane = tid & 31;
    const int wid  = tid >> 5;
    const int row0 = blockIdx.y * 128;
    const int col0 = blockIdx.x * 128;
    const int m0 = (wid & 1) * 64;   // warp m origin within CTA tile
    const int n0 = (wid >> 1) * 32;  // warp n origin within CTA tile

    // Global-load mapping: 256 threads cover 128 rows x 32 cols (float4 each),
    // rows = tid/8 + 32*i, cols = (tid%8)*4  -> fully coalesced 128B segments.
    const int rb = tid >> 3;
    const int cb = (tid & 7) * 4;

    const uint32_t sAh = (uint32_t)__cvta_generic_to_shared(As_hi);
    const uint32_t sAl = (uint32_t)__cvta_generic_to_shared(As_lo);
    const uint32_t sBh = (uint32_t)__cvta_generic_to_shared(Bs_hi);
    const uint32_t sBl = (uint32_t)__cvta_generic_to_shared(Bs_lo);

    float c[4][4][4];
#pragma unroll
    for (int im = 0; im < 4; im++)
#pragma unroll
        for (int jn = 0; jn < 4; jn++)
#pragma unroll
            for (int r = 0; r < 4; r++) c[im][jn][r] = 0.0f;

    float4 av[4], wv[4];
    // Preload tile 0
#pragma unroll
    for (int i = 0; i < 4; i++) {
        av[i] = *(const float4*)(A + (size_t)(row0 + rb + 32 * i) * K + cb);
        wv[i] = *(const float4*)(W + (size_t)(col0 + rb + 32 * i) * K + cb);
    }

    const int kIters = K >> 5;
    for (int it = 0; it < kIters; it++) {
        // Split regs -> smem (hi/lo bf16)
#pragma unroll
        for (int i = 0; i < 4; i++) {
            const int r = rb + 32 * i;
            float vals[4] = {av[i].x, av[i].y, av[i].z, av[i].w};
            __nv_bfloat16 h[4], l[4];
#pragma unroll
            for (int e = 0; e < 4; e++) {
                h[e] = __float2bfloat16(vals[e]);
                l[e] = __float2bfloat16(vals[e] - __bfloat162float(h[e]));
            }
            *(uint2*)&As_hi[r * LDT + cb] = make_uint2(pack_bf16(h[0], h[1]), pack_bf16(h[2], h[3]));
            *(uint2*)&As_lo[r * LDT + cb] = make_uint2(pack_bf16(l[0], l[1]), pack_bf16(l[2], l[3]));
            float wvals[4] = {wv[i].x, wv[i].y, wv[i].z, wv[i].w};
#pragma unroll
            for (int e = 0; e < 4; e++) {
                h[e] = __float2bfloat16(wvals[e]);
                l[e] = __float2bfloat16(wvals[e] - __bfloat162float(h[e]));
            }
            *(uint2*)&Bs_hi[r * LDT + cb] = make_uint2(pack_bf16(h[0], h[1]), pack_bf16(h[2], h[3]));
            *(uint2*)&Bs_lo[r * LDT + cb] = make_uint2(pack_bf16(l[0], l[1]), pack_bf16(l[2], l[3]));
        }
        __syncthreads();

        // Prefetch next tile while mma runs
        if (it + 1 < kIters) {
            const int kt = (it + 1) << 5;
#pragma unroll
            for (int i = 0; i < 4; i++) {
                av[i] = *(const float4*)(A + (size_t)(row0 + rb + 32 * i) * K + kt + cb);
                wv[i] = *(const float4*)(W + (size_t)(col0 + rb + 32 * i) * K + kt + cb);
            }
        }

#pragma unroll
        for (int kk = 0; kk < 32; kk += 16) {
            uint32_t ah[4][4], al[4][4], bh[4][2], bl[4][2];
            const int arow = (lane & 15);
            const int acol = kk + ((lane >> 4) << 3);
#pragma unroll
            for (int im = 0; im < 4; im++) {
                const uint32_t off = (uint32_t)((m0 + im * 16 + arow) * LDT + acol) * 2;
                ldsm_x4(ah[im], sAh + off);
                ldsm_x4(al[im], sAl + off);
            }
            const int brow = (lane & 7);
            const int bcol = kk + ((lane >> 3) & 1) * 8;
#pragma unroll
            for (int jn = 0; jn < 4; jn++) {
                const uint32_t off = (uint32_t)((n0 + jn * 8 + brow) * LDT + bcol) * 2;
                ldsm_x2(bh[jn], sBh + off);
                ldsm_x2(bl[jn], sBl + off);
            }
#pragma unroll
            for (int im = 0; im < 4; im++)
#pragma unroll
                for (int jn = 0; jn < 4; jn++) {
                    mma_bf16(c[im][jn], ah[im], bh[jn]);
                    mma_bf16(c[im][jn], al[im], bh[jn]);
                    mma_bf16(c[im][jn], ah[im], bl[jn]);
                }
        }
        __syncthreads();
    }

    // Epilogue: fragment -> global with bias
#pragma unroll
    for (int jn = 0; jn < 4; jn++) {
        const int nb = col0 + n0 + jn * 8 + (lane & 3) * 2;
        const float b0 = bvec[nb], b1 = bvec[nb + 1];
#pragma unroll
        for (int im = 0; im < 4; im++) {
            const int m = row0 + m0 + im * 16 + (lane >> 2);
            *(float2*)(C + (size_t)m * N + nb) =
                make_float2(c[im][jn][0] + b0, c[im][jn][1] + b1);
            *(float2*)(C + (size_t)(m + 8) * N + nb) =
                make_float2(c[im][jn][2] + b0, c[im][jn][3] + b1);
        }
    }
}

// ---------------------------------------------------------------------------
// Fused attention. Grid: (h, s). 256 threads; thread n owns output row n.
// ---------------------------------------------------------------------------
__global__ void attn_fused_kernel() {
    extern __shared__ float sm[];
    float* ks = sm;                         // [256][32]
    float* vs = sm + N_DIM * DH_DIM;        // [256][32]
    int*   mk = (int*)(sm + 2 * N_DIM * DH_DIM);  // [256]

    const int h = blockIdx.x;
    const int s = blockIdx.y;
    const int n = threadIdx.x;

    const size_t base = ((size_t)(s * N_DIM + n)) * QKV_N + h * DH_DIM;
    float q[DH_DIM];
    {
        const float4* gq = (const float4*)(g_qkv + base);
        float4* qr = (float4*)q;
#pragma unroll
        for (int i = 0; i < 8; i++) qr[i] = gq[i];
        const float4* gk = (const float4*)(g_qkv + base + C_DIM);
        float4* kr = (float4*)(ks + n * DH_DIM);
#pragma unroll
        for (int i = 0; i < 8; i++) kr[i] = gk[i];
        const float4* gv = (const float4*)(g_qkv + base + 2 * C_DIM);
        float4* vr = (float4*)(vs + n * DH_DIM);
#pragma unroll
        for (int i = 0; i < 8; i++) vr[i] = gv[i];
        mk[n] = g_mask[s * N_DIM + n];
    }
    __syncthreads();

    const int mybit = mk[n];
    const float* biasT = g_biasT + (size_t)h * N_DIM * N_DIM;  // [m][n]

    float o[DH_DIM];
#pragma unroll
    for (int d = 0; d < DH_DIM; d++) o[d] = 0.0f;
    float mx = -3.0e38f;
    float l  = 0.0f;

    for (int m0 = 0; m0 < N_DIM; m0 += 8) {
        float sv[8];
#pragma unroll
        for (int j = 0; j < 8; j++) {
            const int m = m0 + j;
            const float4* kr = (const float4*)(ks + m * DH_DIM);
            float acc = 0.0f;
#pragma unroll
            for (int dv = 0; dv < 8; dv++) {
                float4 kv = kr[dv];
                acc += q[dv * 4 + 0] * kv.x + q[dv * 4 + 1] * kv.y +
                       q[dv * 4 + 2] * kv.z + q[dv * 4 + 3] * kv.w;
            }
            acc *= ATT_SCALE;
            if (!(mybit && mk[m])) acc = NEGV;
            sv[j] = acc + biasT[m * N_DIM + n];
        }
        float cm = mx;
#pragma unroll
        for (int j = 0; j < 8; j++) cm = fmaxf(cm, sv[j]);
        float sc = __expf(mx - cm);
        l *= sc;
#pragma unroll
        for (int d = 0; d < DH_DIM; d++) o[d] *= sc;
#pragma unroll
        for (int j = 0; j < 8; j++) {
            float p = __expf(sv[j] - cm);
            l += p;
            const float4* vr = (const float4*)(vs + (m0 + j) * DH_DIM);
#pragma unroll
            for (int dv = 0; dv < 8; dv++) {
                float4 vv = vr[dv];
                o[dv * 4 + 0] += p * vv.x; o[dv * 4 + 1] += p * vv.y;
                o[dv * 4 + 2] += p * vv.z; o[dv * 4 + 3] += p * vv.w;
            }
        }
        mx = cm;
    }

    const float inv = 1.0f / l;
    float4* op = (float4*)(g_att + ((size_t)(s * N_DIM + n)) * C_DIM + h * DH_DIM);
#pragma unroll
    for (int dv = 0; dv < 8; dv++) {
        op[dv] = make_float4(o[dv * 4 + 0] * inv, o[dv * 4 + 1] * inv,
                             o[dv * 4 + 2] * inv, o[dv * 4 + 3] * inv);
    }
}

// ---------------------------------------------------------------------------
// Residual + LayerNorm. One block (256 threads) per row.
// Reads projected output from the reused g_qkv scratch.
// ---------------------------------------------------------------------------
__global__ void ln_kernel(const float* __restrict__ msa,
                          const float* __restrict__ gamma,
                          const float* __restrict__ beta,
                          float* __restrict__ out) {
    __shared__ float red[8];
    const int row = blockIdx.x;
    const int j = threadIdx.x;
    const size_t idx = (size_t)row * C_DIM + j;

    float x = msa[idx] + g_qkv[idx];

    float s = x;
#pragma unroll
    for (int o = 16; o > 0; o >>= 1) s += __shfl_xor_sync(0xffffffffu, s, o);
    if ((j & 31) == 0) red[j >> 5] = s;
    __syncthreads();
    float tot = 0.0f;
#pragma unroll
    for (int w = 0; w < 8; w++) tot += red[w];
    const float mu = tot * (1.0f / C_DIM);
    const float d  = x - mu;

    __syncthreads();
    float v = d * d;
#pragma unroll
    for (int o = 16; o > 0; o >>= 1) v += __shfl_xor_sync(0xffffffffu, v, o);
    if ((j & 31) == 0) red[j >> 5] = v;
    __syncthreads();
    float vt = 0.0f;
#pragma unroll
    for (int w = 0; w < 8; w++) vt += red[w];
    const float var = vt * (1.0f / C_DIM);

    out[idx] = d * rsqrtf(var + LN_EPS) * gamma[j] + beta[j];
}

// ---------------------------------------------------------------------------
// Launch
// ---------------------------------------------------------------------------
#define ATTN_SMEM ((2 * N_DIM * DH_DIM) * 4 + N_DIM * 4)  // 66560 bytes

extern "C" void kernel_launch(void* const* d_in, const int* in_sizes, int n_in,
                              void* d_out, int out_size) {
    const float* msa   = (const float*)d_in[0];
    const float* pair  = (const float*)d_in[1];
    const void*  maskp = d_in[2];
    const float* qkv_w = (const float*)d_in[3];
    const float* qkv_b = (const float*)d_in[4];
    const float* out_w = (const float*)d_in[5];
    const float* out_b = (const float*)d_in[6];
    const float* pb_w  = (const float*)d_in[7];
    const float* pb_b  = (const float*)d_in[8];
    const float* gamma = (const float*)d_in[9];
    const float* beta  = (const float*)d_in[10];
    float* out = (float*)d_out;

    (void)in_sizes; (void)n_in; (void)out_size;

    cudaFuncSetAttribute(attn_fused_kernel,
                         cudaFuncAttributeMaxDynamicSharedMemorySize, ATTN_SMEM);

    void *p_qkv = nullptr, *p_att = nullptr;
    cudaGetSymbolAddress(&p_qkv, g_qkv);
    cudaGetSymbolAddress(&p_att, g_att);

    detect_mask_kernel<<<1, 32>>>((const unsigned char*)maskp);
    norm_mask_kernel<<<ROWS / 256, 256>>>(maskp);
    pair_bias_kernel<<<N_DIM, 256>>>(pair, pb_w, pb_b);

    // QKV projection: [32768,256] x [768,256]^T -> [32768,768]  (tensor cores)
    gemm_bf16x3_nt<<<dim3(QKV_N / 128, ROWS / 128), 256>>>(
        msa, qkv_w, qkv_b, (float*)p_qkv, ROWS, QKV_N, C_DIM);

    // Fused attention per (h, s)
    attn_fused_kernel<<<dim3(H_DIM, S_DIM), 256, ATTN_SMEM>>>();

    // Output projection: [32768,256] x [256,256]^T -> [32768,256]  (tensor cores)
    // Destination reuses g_qkv scratch (qkv values are dead after attention).
    gemm_bf16x3_nt<<<dim3(C_DIM / 128, ROWS / 128), 256>>>(
        (const float*)p_att, out_w, out_b, (float*)p_qkv, ROWS, C_DIM, C_DIM);

    // Residual + LayerNorm -> d_out
    ln_kernel<<<ROWS, 256>>>(msa, gamma, beta, out);
}

// round 7
// speedup vs baseline: 1.8900x; 1.3992x over previous
#include <cuda_runtime.h>
#include <cuda_bf16.h>
#include <cstdint>
#include <cstddef>

// Problem constants
#define S_DIM 128
#define N_DIM 256
#define C_DIM 256
#define H_DIM 8
#define DH_DIM 32
#define PD_DIM 128
#define ROWS (S_DIM * N_DIM)          // 32768 token rows
#define QKV_N 768                      // 3*C
#define ATT_SCALE 0.17677669529663687f // 32^-0.5
#define NEGV (-1000000000.0f)
#define LN_EPS 1e-5f

// ---------------------------------------------------------------------------
// Scratch (static device allocations — no runtime malloc allowed).
// g_qkv is dead after the attention kernel; the out-projection reuses its
// first ROWS*C_DIM floats as its destination (disjoint lifetimes).
// ---------------------------------------------------------------------------
__device__ float g_qkv[(size_t)ROWS * QKV_N];              // 100.7 MB
__device__ float g_biasB[(size_t)H_DIM * N_DIM * N_DIM];   // 2 MB, layout [h][n][m]
__device__ float g_att[(size_t)ROWS * C_DIM];              // 33.6 MB
__device__ int   g_mask[ROWS];
__device__ int   g_mask_mode;

// ---------------------------------------------------------------------------
// Mask dtype detection (jax bool on-wire may be int32 / byte / float32).
// ---------------------------------------------------------------------------
__global__ void detect_mask_kernel(const unsigned char* __restrict__ p) {
    if (threadIdx.x == 0) {
        const unsigned int* w = (const unsigned int*)p;
        bool is_i32 = true, is_f32 = true;
        for (int i = 0; i < 256; i++) {
            unsigned int v = w[i];
            if (v > 1u) is_i32 = false;
            if (v != 0u && v != 0x3f800000u) is_f32 = false;
        }
        g_mask_mode = is_i32 ? 0 : (is_f32 ? 2 : 1);
    }
}

__global__ void norm_mask_kernel(const void* __restrict__ p) {
    int i = blockIdx.x * blockDim.x + threadIdx.x;
    if (i >= ROWS) return;
    int mode = g_mask_mode;
    int v;
    if (mode == 0)      v = (((const int*)p)[i] != 0);
    else if (mode == 1) v = (((const unsigned char*)p)[i] != 0);
    else                v = (((const float*)p)[i] != 0.0f);
    g_mask[i] = v;
}

// ---------------------------------------------------------------------------
// Pair bias: biasB[h][n][m] = dot(pair[n][m][:], pb_w[h][:]) + pb_b[h]
// (n = query, m = key). Block = n, thread = m -> coalesced writes.
// ---------------------------------------------------------------------------
__global__ void pair_bias_kernel(const float* __restrict__ pair,
                                 const float* __restrict__ pb_w,
                                 const float* __restrict__ pb_b) {
    __shared__ float w[H_DIM][PD_DIM];
    __shared__ float bb[H_DIM];
    int tid = threadIdx.x;
    for (int i = tid; i < H_DIM * PD_DIM; i += 256) w[i >> 7][i & 127] = pb_w[i];
    if (tid < H_DIM) bb[tid] = pb_b[tid];
    __syncthreads();

    int n = blockIdx.x;
    int m = tid;
    const float4* pr = (const float4*)(pair + ((size_t)n * N_DIM + m) * PD_DIM);
    float acc[H_DIM];
#pragma unroll
    for (int h = 0; h < H_DIM; h++) acc[h] = bb[h];
#pragma unroll 4
    for (int dv = 0; dv < PD_DIM / 4; dv++) {
        float4 pv = pr[dv];
#pragma unroll
        for (int h = 0; h < H_DIM; h++) {
            float4 wv = *(const float4*)&w[h][dv * 4];
            acc[h] += pv.x * wv.x + pv.y * wv.y + pv.z * wv.z + pv.w * wv.w;
        }
    }
#pragma unroll
    for (int h = 0; h < H_DIM; h++)
        g_biasB[((size_t)h * N_DIM + n) * N_DIM + m] = acc[h];
}

// ---------------------------------------------------------------------------
// mma / ldmatrix helpers (validated in R6 GEMM)
// ---------------------------------------------------------------------------
__device__ __forceinline__ void mma_bf16(float* c, const uint32_t* a, const uint32_t* b) {
    asm volatile(
        "mma.sync.aligned.m16n8k16.row.col.f32.bf16.bf16.f32 "
        "{%0,%1,%2,%3}, {%4,%5,%6,%7}, {%8,%9}, {%0,%1,%2,%3};"
        : "+f"(c[0]), "+f"(c[1]), "+f"(c[2]), "+f"(c[3])
        : "r"(a[0]), "r"(a[1]), "r"(a[2]), "r"(a[3]), "r"(b[0]), "r"(b[1]));
}

__device__ __forceinline__ void ldsm_x4(uint32_t* r, uint32_t addr) {
    asm volatile("ldmatrix.sync.aligned.m8n8.x4.shared.b16 {%0,%1,%2,%3}, [%4];"
                 : "=r"(r[0]), "=r"(r[1]), "=r"(r[2]), "=r"(r[3]) : "r"(addr));
}

__device__ __forceinline__ void ldsm_x2(uint32_t* r, uint32_t addr) {
    asm volatile("ldmatrix.sync.aligned.m8n8.x2.shared.b16 {%0,%1}, [%2];"
                 : "=r"(r[0]), "=r"(r[1]) : "r"(addr));
}

__device__ __forceinline__ uint32_t pack_bf16(__nv_bfloat16 a, __nv_bfloat16 b) {
    __nv_bfloat162 t = __halves2bfloat162(a, b);
    return *(uint32_t*)&t;
}

__device__ __forceinline__ uint32_t pack_hi(float a, float b) {
    return pack_bf16(__float2bfloat16(a), __float2bfloat16(b));
}
__device__ __forceinline__ uint32_t pack_lo(float a, float b) {
    __nv_bfloat16 ha = __float2bfloat16(a), hb = __float2bfloat16(b);
    return pack_bf16(__float2bfloat16(a - __bfloat162float(ha)),
                     __float2bfloat16(b - __bfloat162float(hb)));
}

// ---------------------------------------------------------------------------
// Tensor-core GEMM (NT): C[M,N] = A[M,K] @ W[N,K]^T + bias[N]   (unchanged R6)
// ---------------------------------------------------------------------------
#define LDT 40  // padded smem row stride in bf16 elements (32 data + 8 pad)

__global__ __launch_bounds__(256)
void gemm_bf16x3_nt(const float* __restrict__ A,
                    const float* __restrict__ W,
                    const float* __restrict__ bvec,
                    float* __restrict__ C,
                    int M, int N, int K) {
    __shared__ __align__(16) uint16_t As_hi[128 * LDT];
    __shared__ __align__(16) uint16_t As_lo[128 * LDT];
    __shared__ __align__(16) uint16_t Bs_hi[128 * LDT];
    __shared__ __align__(16) uint16_t Bs_lo[128 * LDT];

    const int tid  = threadIdx.x;
    const int lane = tid & 31;
    const int wid  = tid >> 5;
    const int row0 = blockIdx.y * 128;
    const int col0 = blockIdx.x * 128;
    const int m0 = (wid & 1) * 64;
    const int n0 = (wid >> 1) * 32;

    const int rb = tid >> 3;
    const int cb = (tid & 7) * 4;

    const uint32_t sAh = (uint32_t)__cvta_generic_to_shared(As_hi);
    const uint32_t sAl = (uint32_t)__cvta_generic_to_shared(As_lo);
    const uint32_t sBh = (uint32_t)__cvta_generic_to_shared(Bs_hi);
    const uint32_t sBl = (uint32_t)__cvta_generic_to_shared(Bs_lo);

    float c[4][4][4];
#pragma unroll
    for (int im = 0; im < 4; im++)
#pragma unroll
        for (int jn = 0; jn < 4; jn++)
#pragma unroll
            for (int r = 0; r < 4; r++) c[im][jn][r] = 0.0f;

    float4 av[4], wv[4];
#pragma unroll
    for (int i = 0; i < 4; i++) {
        av[i] = *(const float4*)(A + (size_t)(row0 + rb + 32 * i) * K + cb);
        wv[i] = *(const float4*)(W + (size_t)(col0 + rb + 32 * i) * K + cb);
    }

    const int kIters = K >> 5;
    for (int it = 0; it < kIters; it++) {
#pragma unroll
        for (int i = 0; i < 4; i++) {
            const int r = rb + 32 * i;
            *(uint2*)&As_hi[r * LDT + cb] = make_uint2(pack_hi(av[i].x, av[i].y), pack_hi(av[i].z, av[i].w));
            *(uint2*)&As_lo[r * LDT + cb] = make_uint2(pack_lo(av[i].x, av[i].y), pack_lo(av[i].z, av[i].w));
            *(uint2*)&Bs_hi[r * LDT + cb] = make_uint2(pack_hi(wv[i].x, wv[i].y), pack_hi(wv[i].z, wv[i].w));
            *(uint2*)&Bs_lo[r * LDT + cb] = make_uint2(pack_lo(wv[i].x, wv[i].y), pack_lo(wv[i].z, wv[i].w));
        }
        __syncthreads();

        if (it + 1 < kIters) {
            const int kt = (it + 1) << 5;
#pragma unroll
            for (int i = 0; i < 4; i++) {
                av[i] = *(const float4*)(A + (size_t)(row0 + rb + 32 * i) * K + kt + cb);
                wv[i] = *(const float4*)(W + (size_t)(col0 + rb + 32 * i) * K + kt + cb);
            }
        }

#pragma unroll
        for (int kk = 0; kk < 32; kk += 16) {
            uint32_t ah[4][4], al[4][4], bh[4][2], bl[4][2];
            const int arow = (lane & 15);
            const int acol = kk + ((lane >> 4) << 3);
#pragma unroll
            for (int im = 0; im < 4; im++) {
                const uint32_t off = (uint32_t)((m0 + im * 16 + arow) * LDT + acol) * 2;
                ldsm_x4(ah[im], sAh + off);
                ldsm_x4(al[im], sAl + off);
            }
            const int brow = (lane & 7);
            const int bcol = kk + ((lane >> 3) & 1) * 8;
#pragma unroll
            for (int jn = 0; jn < 4; jn++) {
                const uint32_t off = (uint32_t)((n0 + jn * 8 + brow) * LDT + bcol) * 2;
                ldsm_x2(bh[jn], sBh + off);
                ldsm_x2(bl[jn], sBl + off);
            }
#pragma unroll
            for (int im = 0; im < 4; im++)
#pragma unroll
                for (int jn = 0; jn < 4; jn++) {
                    mma_bf16(c[im][jn], ah[im], bh[jn]);
                    mma_bf16(c[im][jn], al[im], bh[jn]);
                    mma_bf16(c[im][jn], ah[im], bl[jn]);
                }
        }
        __syncthreads();
    }

#pragma unroll
    for (int jn = 0; jn < 4; jn++) {
        const int nb = col0 + n0 + jn * 8 + (lane & 3) * 2;
        const float b0 = bvec[nb], b1 = bvec[nb + 1];
#pragma unroll
        for (int im = 0; im < 4; im++) {
            const int m = row0 + m0 + im * 16 + (lane >> 2);
            *(float2*)(C + (size_t)m * N + nb) =
                make_float2(c[im][jn][0] + b0, c[im][jn][1] + b1);
            *(float2*)(C + (size_t)(m + 8) * N + nb) =
                make_float2(c[im][jn][2] + b0, c[im][jn][3] + b1);
        }
    }
}

// ---------------------------------------------------------------------------
// Tensor-core fused attention. Grid (h, s), 256 threads (8 warps).
// Warp w owns query rows [32w, 32w+32). Keys processed in blocks of 64 with
// online softmax. QK^T and P*V both bf16 hi/lo 3-pass mma.
// Smem: K tile [256][LDT] hi/lo, V^T tile [32][264] hi/lo, mask[256].
// ---------------------------------------------------------------------------
#define VLD 264  // VT row stride in bf16 (256 keys + 8 pad); 528B = 33*16 ok
#define ATTN_SMEM2 (2*(256*LDT*2) + 2*(32*VLD*2) + 256*4)  // 75776 bytes

__global__ __launch_bounds__(256)
void attn_mma_kernel() {
    extern __shared__ __align__(16) char smb[];
    uint16_t* Ks_hi = (uint16_t*)smb;                       // [256][LDT]
    uint16_t* Ks_lo = (uint16_t*)(smb + 20480);
    uint16_t* VT_hi = (uint16_t*)(smb + 40960);             // [32][VLD]
    uint16_t* VT_lo = (uint16_t*)(smb + 57856);
    int*      mk    = (int*)     (smb + 74752);             // [256]

    const int h = blockIdx.x;
    const int s = blockIdx.y;
    const int tid  = threadIdx.x;
    const int lane = tid & 31;
    const int wid  = tid >> 5;
    const int w32  = wid * 32;

    const uint32_t sKh = (uint32_t)__cvta_generic_to_shared(Ks_hi);
    const uint32_t sKl = (uint32_t)__cvta_generic_to_shared(Ks_lo);
    const uint32_t sVh = (uint32_t)__cvta_generic_to_shared(VT_hi);
    const uint32_t sVl = (uint32_t)__cvta_generic_to_shared(VT_lo);

    // ---- Stage K (row-major) and V (transposed) into smem; mask too.
    {
        const float* kv = g_qkv + (size_t)(s * N_DIM + tid) * QKV_N + h * DH_DIM;
        float kr[32], vr[32];
#pragma unroll
        for (int i = 0; i < 8; i++) {
            *(float4*)&kr[i * 4] = *(const float4*)(kv + C_DIM + i * 4);
            *(float4*)&vr[i * 4] = *(const float4*)(kv + 2 * C_DIM + i * 4);
        }
#pragma unroll
        for (int i = 0; i < 8; i++) {
            *(uint2*)&Ks_hi[tid * LDT + i * 4] =
                make_uint2(pack_hi(kr[i*4], kr[i*4+1]), pack_hi(kr[i*4+2], kr[i*4+3]));
            *(uint2*)&Ks_lo[tid * LDT + i * 4] =
                make_uint2(pack_lo(kr[i*4], kr[i*4+1]), pack_lo(kr[i*4+2], kr[i*4+3]));
        }
#pragma unroll
        for (int d = 0; d < 32; d++) {
            __nv_bfloat16 vh = __float2bfloat16(vr[d]);
            __nv_bfloat16 vl = __float2bfloat16(vr[d] - __bfloat162float(vh));
            VT_hi[d * VLD + tid] = *(uint16_t*)&vh;
            VT_lo[d * VLD + tid] = *(uint16_t*)&vl;
        }
        mk[tid] = g_mask[s * N_DIM + tid];
    }
    __syncthreads();

    // ---- Q fragments: built directly from global (rows w32..w32+31).
    // A-frag layout m16n8k16: reg0=(r,2q+{0,1}), reg1=(r+8,..), reg2=(r,+8), reg3=(r+8,+8)
    uint32_t qh[2][2][4], ql[2][2][4];
    {
        const int qoff = 2 * (lane & 3);
#pragma unroll
        for (int i = 0; i < 2; i++) {
            const int r0 = w32 + 16 * i + (lane >> 2);
            const float* q0 = g_qkv + (size_t)(s * N_DIM + r0) * QKV_N + h * DH_DIM;
            const float* q8 = q0 + 8 * QKV_N;   // row r0+8
#pragma unroll
            for (int t = 0; t < 2; t++) {
                float2 e0 = *(const float2*)(q0 + 16 * t + qoff);
                float2 e1 = *(const float2*)(q8 + 16 * t + qoff);
                float2 e2 = *(const float2*)(q0 + 16 * t + 8 + qoff);
                float2 e3 = *(const float2*)(q8 + 16 * t + 8 + qoff);
                qh[i][t][0] = pack_hi(e0.x, e0.y); ql[i][t][0] = pack_lo(e0.x, e0.y);
                qh[i][t][1] = pack_hi(e1.x, e1.y); ql[i][t][1] = pack_lo(e1.x, e1.y);
                qh[i][t][2] = pack_hi(e2.x, e2.y); ql[i][t][2] = pack_lo(e2.x, e2.y);
                qh[i][t][3] = pack_hi(e3.x, e3.y); ql[i][t][3] = pack_lo(e3.x, e3.y);
            }
        }
    }

    float O[2][4][4];
#pragma unroll
    for (int i = 0; i < 2; i++)
#pragma unroll
        for (int j = 0; j < 4; j++)
#pragma unroll
            for (int r = 0; r < 4; r++) O[i][j][r] = 0.0f;
    float mx[2][2] = {{-3.0e38f, -3.0e38f}, {-3.0e38f, -3.0e38f}};
    float lsum[2][2] = {{0.0f, 0.0f}, {0.0f, 0.0f}};

    const int mr[2][2] = {{mk[w32 + (lane >> 2)], mk[w32 + 8 + (lane >> 2)]},
                          {mk[w32 + 16 + (lane >> 2)], mk[w32 + 24 + (lane >> 2)]}};

    for (int kb = 0; kb < 4; kb++) {
        // ---- S = Q @ K^T for this 64-key block
        float S[2][8][4];
#pragma unroll
        for (int i = 0; i < 2; i++)
#pragma unroll
            for (int j = 0; j < 8; j++)
#pragma unroll
                for (int r = 0; r < 4; r++) S[i][j][r] = 0.0f;

#pragma unroll
        for (int t = 0; t < 2; t++) {   // dh k16-slices
            uint32_t kh[8][2], kl[8][2];
            const int brow = lane & 7;
            const int bcol = 16 * t + ((lane >> 3) & 1) * 8;
#pragma unroll
            for (int j = 0; j < 8; j++) {
                const uint32_t off = (uint32_t)((kb * 64 + j * 8 + brow) * LDT + bcol) * 2;
                ldsm_x2(kh[j], sKh + off);
                ldsm_x2(kl[j], sKl + off);
            }
#pragma unroll
            for (int i = 0; i < 2; i++)
#pragma unroll
                for (int j = 0; j < 8; j++) {
                    mma_bf16(S[i][j], qh[i][t], kh[j]);
                    mma_bf16(S[i][j], ql[i][t], kh[j]);
                    mma_bf16(S[i][j], qh[i][t], kl[j]);
                }
        }

        // ---- mask, scale, bias (exact reference order)
#pragma unroll
        for (int i = 0; i < 2; i++) {
            const int r0 = w32 + 16 * i + (lane >> 2);
            const float* bb0 = g_biasB + ((size_t)(h * N_DIM + r0)) * N_DIM;
            const float* bb8 = bb0 + 8 * N_DIM;
#pragma unroll
            for (int j = 0; j < 8; j++) {
                const int m = kb * 64 + j * 8 + 2 * (lane & 3);
                const int mc0 = mk[m], mc1 = mk[m + 1];
                float2 b0 = *(const float2*)(bb0 + m);
                float2 b8 = *(const float2*)(bb8 + m);
                float v0 = (mr[i][0] && mc0) ? S[i][j][0] * ATT_SCALE : NEGV;
                float v1 = (mr[i][0] && mc1) ? S[i][j][1] * ATT_SCALE : NEGV;
                float v2 = (mr[i][1] && mc0) ? S[i][j][2] * ATT_SCALE : NEGV;
                float v3 = (mr[i][1] && mc1) ? S[i][j][3] * ATT_SCALE : NEGV;
                S[i][j][0] = v0 + b0.x; S[i][j][1] = v1 + b0.y;
                S[i][j][2] = v2 + b8.x; S[i][j][3] = v3 + b8.y;
            }
        }

        // ---- online softmax (per row; rows live in lane quads)
#pragma unroll
        for (int i = 0; i < 2; i++) {
            float rm0 = -3.0e38f, rm1 = -3.0e38f;
#pragma unroll
            for (int j = 0; j < 8; j++) {
                rm0 = fmaxf(rm0, fmaxf(S[i][j][0], S[i][j][1]));
                rm1 = fmaxf(rm1, fmaxf(S[i][j][2], S[i][j][3]));
            }
            rm0 = fmaxf(rm0, __shfl_xor_sync(0xffffffffu, rm0, 1));
            rm0 = fmaxf(rm0, __shfl_xor_sync(0xffffffffu, rm0, 2));
            rm1 = fmaxf(rm1, __shfl_xor_sync(0xffffffffu, rm1, 1));
            rm1 = fmaxf(rm1, __shfl_xor_sync(0xffffffffu, rm1, 2));
            const float cm0 = fmaxf(mx[i][0], rm0);
            const float cm1 = fmaxf(mx[i][1], rm1);
            const float sc0 = __expf(mx[i][0] - cm0);
            const float sc1 = __expf(mx[i][1] - cm1);
            mx[i][0] = cm0; mx[i][1] = cm1;
            lsum[i][0] *= sc0; lsum[i][1] *= sc1;
#pragma unroll
            for (int jd = 0; jd < 4; jd++) {
                O[i][jd][0] *= sc0; O[i][jd][1] *= sc0;
                O[i][jd][2] *= sc1; O[i][jd][3] *= sc1;
            }
            float s0 = 0.0f, s1 = 0.0f;
#pragma unroll
            for (int j = 0; j < 8; j++) {
                float p0 = __expf(S[i][j][0] - cm0);
                float p1 = __expf(S[i][j][1] - cm0);
                float p2 = __expf(S[i][j][2] - cm1);
                float p3 = __expf(S[i][j][3] - cm1);
                S[i][j][0] = p0; S[i][j][1] = p1; S[i][j][2] = p2; S[i][j][3] = p3;
                s0 += p0 + p1; s1 += p2 + p3;
            }
            s0 += __shfl_xor_sync(0xffffffffu, s0, 1);
            s0 += __shfl_xor_sync(0xffffffffu, s0, 2);
            s1 += __shfl_xor_sync(0xffffffffu, s1, 1);
            s1 += __shfl_xor_sync(0xffffffffu, s1, 2);
            lsum[i][0] += s0; lsum[i][1] += s1;
        }

        // ---- O += P @ V  (P from S accumulators via C->A fragment packing)
#pragma unroll
        for (int t = 0; t < 4; t++) {   // key k16-slices within the block
            uint32_t vh[4][2], vl[4][2];
            const int brow = lane & 7;
            const int bcol = kb * 64 + 16 * t + ((lane >> 3) & 1) * 8;
#pragma unroll
            for (int jd = 0; jd < 4; jd++) {
                const uint32_t off = (uint32_t)((jd * 8 + brow) * VLD + bcol) * 2;
                ldsm_x2(vh[jd], sVh + off);
                ldsm_x2(vl[jd], sVl + off);
            }
#pragma unroll
            for (int i = 0; i < 2; i++) {
                uint32_t ph[4], pl[4];
                ph[0] = pack_hi(S[i][2*t][0],   S[i][2*t][1]);
                ph[1] = pack_hi(S[i][2*t][2],   S[i][2*t][3]);
                ph[2] = pack_hi(S[i][2*t+1][0], S[i][2*t+1][1]);
                ph[3] = pack_hi(S[i][2*t+1][2], S[i][2*t+1][3]);
                pl[0] = pack_lo(S[i][2*t][0],   S[i][2*t][1]);
                pl[1] = pack_lo(S[i][2*t][2],   S[i][2*t][3]);
                pl[2] = pack_lo(S[i][2*t+1][0], S[i][2*t+1][1]);
                pl[3] = pack_lo(S[i][2*t+1][2], S[i][2*t+1][3]);
#pragma unroll
                for (int jd = 0; jd < 4; jd++) {
                    mma_bf16(O[i][jd], ph, vh[jd]);
                    mma_bf16(O[i][jd], pl, vh[jd]);
                    mma_bf16(O[i][jd], ph, vl[jd]);
                }
            }
        }
    }

    // ---- normalize + write
#pragma unroll
    for (int i = 0; i < 2; i++) {
        const float inv0 = 1.0f / lsum[i][0];
        const float inv1 = 1.0f / lsum[i][1];
        const int r0 = w32 + 16 * i + (lane >> 2);
        float* o0 = g_att + (size_t)(s * N_DIM + r0) * C_DIM + h * DH_DIM;
        float* o8 = o0 + 8 * C_DIM;
#pragma unroll
        for (int jd = 0; jd < 4; jd++) {
            const int dh = jd * 8 + 2 * (lane & 3);
            *(float2*)(o0 + dh) = make_float2(O[i][jd][0] * inv0, O[i][jd][1] * inv0);
            *(float2*)(o8 + dh) = make_float2(O[i][jd][2] * inv1, O[i][jd][3] * inv1);
        }
    }
}

// ---------------------------------------------------------------------------
// Residual + LayerNorm. One block (256 threads) per row.
// ---------------------------------------------------------------------------
__global__ void ln_kernel(const float* __restrict__ msa,
                          const float* __restrict__ gamma,
                          const float* __restrict__ beta,
                          float* __restrict__ out) {
    __shared__ float red[8];
    const int row = blockIdx.x;
    const int j = threadIdx.x;
    const size_t idx = (size_t)row * C_DIM + j;

    float x = msa[idx] + g_qkv[idx];

    float s = x;
#pragma unroll
    for (int o = 16; o > 0; o >>= 1) s += __shfl_xor_sync(0xffffffffu, s, o);
    if ((j & 31) == 0) red[j >> 5] = s;
    __syncthreads();
    float tot = 0.0f;
#pragma unroll
    for (int w = 0; w < 8; w++) tot += red[w];
    const float mu = tot * (1.0f / C_DIM);
    const float d  = x - mu;

    __syncthreads();
    float v = d * d;
#pragma unroll
    for (int o = 16; o > 0; o >>= 1) v += __shfl_xor_sync(0xffffffffu, v, o);
    if ((j & 31) == 0) red[j >> 5] = v;
    __syncthreads();
    float vt = 0.0f;
#pragma unroll
    for (int w = 0; w < 8; w++) vt += red[w];
    const float var = vt * (1.0f / C_DIM);

    out[idx] = d * rsqrtf(var + LN_EPS) * gamma[j] + beta[j];
}

// ---------------------------------------------------------------------------
// Launch
// ---------------------------------------------------------------------------
extern "C" void kernel_launch(void* const* d_in, const int* in_sizes, int n_in,
                              void* d_out, int out_size) {
    const float* msa   = (const float*)d_in[0];
    const float* pair  = (const float*)d_in[1];
    const void*  maskp = d_in[2];
    const float* qkv_w = (const float*)d_in[3];
    const float* qkv_b = (const float*)d_in[4];
    const float* out_w = (const float*)d_in[5];
    const float* out_b = (const float*)d_in[6];
    const float* pb_w  = (const float*)d_in[7];
    const float* pb_b  = (const float*)d_in[8];
    const float* gamma = (const float*)d_in[9];
    const float* beta  = (const float*)d_in[10];
    float* out = (float*)d_out;

    (void)in_sizes; (void)n_in; (void)out_size;

    cudaFuncSetAttribute(attn_mma_kernel,
                         cudaFuncAttributeMaxDynamicSharedMemorySize, ATTN_SMEM2);

    void *p_qkv = nullptr, *p_att = nullptr;
    cudaGetSymbolAddress(&p_qkv, g_qkv);
    cudaGetSymbolAddress(&p_att, g_att);

    detect_mask_kernel<<<1, 32>>>((const unsigned char*)maskp);
    norm_mask_kernel<<<ROWS / 256, 256>>>(maskp);
    pair_bias_kernel<<<N_DIM, 256>>>(pair, pb_w, pb_b);

    // QKV projection: [32768,256] x [768,256]^T -> [32768,768]  (tensor cores)
    gemm_bf16x3_nt<<<dim3(QKV_N / 128, ROWS / 128), 256>>>(
        msa, qkv_w, qkv_b, (float*)p_qkv, ROWS, QKV_N, C_DIM);

    // Fused attention per (h, s) — tensor cores
    attn_mma_kernel<<<dim3(H_DIM, S_DIM), 256, ATTN_SMEM2>>>();

    // Output projection: [32768,256] x [256,256]^T -> [32768,256]  (tensor cores)
    gemm_bf16x3_nt<<<dim3(C_DIM / 128, ROWS / 128), 256>>>(
        (const float*)p_att, out_w, out_b, (float*)p_qkv, ROWS, C_DIM, C_DIM);

    // Residual + LayerNorm -> d_out
    ln_kernel<<<ROWS, 256>>>(msa, gamma, beta, out);
}